// round 12
// baseline (speedup 1.0000x reference)
#include <cuda_runtime.h>
#include <math.h>
#include <stdint.h>

#define NJ 34
#define NV 500000
#define NB 32
#define NQF (NV * 3 / 4)       // 375000 output float4s per batch plane
#define BLK 128
#define NWARPS (BLK / 32)      // 4
#define NBLOCKS ((NV + BLK - 1) / BLK)   // 3907
#define F4_PER_BLK (BLK * 3 / 4)         // 96 float4s per plane per block
#define W_STRIDE 1088          // floats of weights per warp (32*34)

__constant__ int c_parents[NJ] = {
    -1, 0, 1, 2, 2, 4, 5, 6, 7, 8, 9, 7, 11, 12, 7, 14, 15, 2,
    17, 18, 19, 20, 21, 22, 20, 24, 25, 20, 27, 28, 0, 30, 0, 32
};

__global__ __launch_bounds__(BLK) void fused_lbs_kernel(
    const float* __restrict__ pose,
    const float* __restrict__ joints,
    const float* __restrict__ weights,
    const float* __restrict__ v_template,
    const float* __restrict__ local_adjust,
    const float* __restrict__ disp,
    const float* __restrict__ scale,
    const float* __restrict__ est,
    float4* __restrict__ out)
{
    __shared__ __align__(16) float sA[NJ * 12];
    __shared__ __align__(16) float4 sRot[3 * NB];          // rotated addends
    __shared__ __align__(16) float sW[NWARPS * W_STRIDE];  // 17 KB staging
    __shared__ __align__(16) float sVP[BLK * 3];           // posed verts

    // phase-0 scratch aliased inside sW (dead until staging)
    float* sT = sW;           // NJ*12 = 408 floats
    float* sJ = sW + 512;     // NJ*3

    const int t = threadIdx.x;
    const int w = t >> 5;
    const int l = t & 31;

    // ---- phase 0a: rotated base table + joints ----
    if (t < 3 * NB) {
        int m = t >> 5;          // 0..2
        int p = t & 31;          // plane
        float b0 = disp[0] + est[p * 3 + 0];
        float b1 = disp[1] + est[p * 3 + 1];
        float b2 = disp[2] + est[p * 3 + 2];
        float r0 = (m == 0) ? b0 : ((m == 1) ? b1 : b2);
        float r1 = (m == 0) ? b1 : ((m == 1) ? b2 : b0);
        float r2 = (m == 0) ? b2 : ((m == 1) ? b0 : b1);
        sRot[m * NB + p] = make_float4(r0, r1, r2, r0);
    }
    if (t < NJ * 3) sJ[t] = joints[t];
    __syncthreads();

    // ---- phase 0b: local transforms ----
    if (t < NJ) {
        float rx = pose[t * 3 + 0], ry = pose[t * 3 + 1], rz = pose[t * 3 + 2];
        float ang = sqrtf(rx * rx + ry * ry + rz * rz + 1e-8f);
        float inv = 1.0f / ang;
        float x = rx * inv, y = ry * inv, z = rz * inv;
        float s = sinf(ang), c = cosf(ang), oc = 1.0f - c;
        int p = c_parents[t];
        float tx = sJ[t * 3 + 0], ty = sJ[t * 3 + 1], tz = sJ[t * 3 + 2];
        if (p >= 0) { tx -= sJ[p * 3 + 0]; ty -= sJ[p * 3 + 1]; tz -= sJ[p * 3 + 2]; }
        float* T = sT + t * 12;
        T[0] = c + oc * x * x;      T[1] = oc * x * y - s * z;  T[2]  = oc * x * z + s * y;  T[3]  = tx;
        T[4] = oc * x * y + s * z;  T[5] = c + oc * y * y;      T[6]  = oc * y * z - s * x;  T[7]  = ty;
        T[8] = oc * x * z - s * y;  T[9] = oc * y * z + s * x;  T[10] = c + oc * z * z;      T[11] = tz;
    }
    __syncthreads();

    // ---- phase 0c: ancestor-chain composition -> A (scale folded) ----
    if (t < NJ) {
        int chain[16];
        int d = 0;
        for (int n = t; n >= 0; n = c_parents[n]) chain[d++] = n;
        float G[12];
        const float* Tr = sT + chain[d - 1] * 12;
        #pragma unroll
        for (int k = 0; k < 12; k++) G[k] = Tr[k];
        for (int k = d - 2; k >= 0; k--) {
            const float* Tc = sT + chain[k] * 12;
            float C[12];
            #pragma unroll
            for (int r = 0; r < 3; r++) {
                float g0 = G[r * 4 + 0], g1 = G[r * 4 + 1], g2 = G[r * 4 + 2], g3 = G[r * 4 + 3];
                C[r * 4 + 0] = g0 * Tc[0] + g1 * Tc[4] + g2 * Tc[8];
                C[r * 4 + 1] = g0 * Tc[1] + g1 * Tc[5] + g2 * Tc[9];
                C[r * 4 + 2] = g0 * Tc[2] + g1 * Tc[6] + g2 * Tc[10];
                C[r * 4 + 3] = g0 * Tc[3] + g1 * Tc[7] + g2 * Tc[11] + g3;
            }
            #pragma unroll
            for (int k2 = 0; k2 < 12; k2++) G[k2] = C[k2];
        }
        float sc = scale[0];
        float jx = sJ[t * 3 + 0], jy = sJ[t * 3 + 1], jz = sJ[t * 3 + 2];
        #pragma unroll
        for (int r = 0; r < 3; r++) {
            float tr = G[r * 4 + 0] * jx + G[r * 4 + 1] * jy + G[r * 4 + 2] * jz;
            sA[t * 12 + r * 4 + 0] = sc * G[r * 4 + 0];
            sA[t * 12 + r * 4 + 1] = sc * G[r * 4 + 1];
            sA[t * 12 + r * 4 + 2] = sc * G[r * 4 + 2];
            sA[t * 12 + r * 4 + 3] = sc * (G[r * 4 + 3] - tr);
        }
    }
    __syncthreads();   // sT/sJ dead; sW free for weight staging

    // ---- phase 1a: warp-cooperative coalesced weight staging (R10 path) ----
    const int block_base = blockIdx.x * BLK;
    const int warp_base = block_base + w * 32;
    const int v = block_base + t;

    if (warp_base < NV) {
        const size_t f4_base = (size_t)warp_base * 34 / 4;
        const size_t f4_total = (size_t)NV * 34 / 4;
        const float4* srcw = (const float4*)weights;
        float4* dstw = (float4*)(sW + w * W_STRIDE);
        #pragma unroll
        for (int i = 0; i < 9; i++) {
            int idx = i * 32 + l;
            if (idx < 272 && f4_base + idx < f4_total)
                dstw[idx] = __ldcs(srcw + f4_base + idx);
        }
    }

    // vt/la loads issued while staging is in flight
    float vtx = 0.f, vty = 0.f, vtz = 0.f, lax = 0.f, lay = 0.f, laz = 0.f;
    if (v < NV) {
        const float* vtp = v_template + (size_t)v * 3;
        const float* lap = local_adjust + (size_t)v * 3;
        vtx = __ldcs(vtp + 0); vty = __ldcs(vtp + 1); vtz = __ldcs(vtp + 2);
        lax = __ldcs(lap + 0); lay = __ldcs(lap + 1); laz = __ldcs(lap + 2);
    }
    __syncwarp();

    // ---- phase 1b: skin (R5 math) ----
    float vp0 = 0.0f, vp1 = 0.0f, vp2 = 0.0f;
    if (v < NV) {
        float T[12];
        #pragma unroll
        for (int k = 0; k < 12; k++) T[k] = 0.0f;

        const float2* wp = (const float2*)(sW + w * W_STRIDE + l * 34);
        #pragma unroll
        for (int k = 0; k < 17; k++) {
            float2 w2 = wp[k];
            {
                const float* Aj = sA + (2 * k) * 12;
                float a[12];
                *(float4*)(a + 0) = *(const float4*)(Aj + 0);
                *(float4*)(a + 4) = *(const float4*)(Aj + 4);
                *(float4*)(a + 8) = *(const float4*)(Aj + 8);
                #pragma unroll
                for (int q = 0; q < 12; q++) T[q] += w2.x * a[q];
            }
            {
                const float* Aj = sA + (2 * k + 1) * 12;
                float a[12];
                *(float4*)(a + 0) = *(const float4*)(Aj + 0);
                *(float4*)(a + 4) = *(const float4*)(Aj + 4);
                *(float4*)(a + 8) = *(const float4*)(Aj + 8);
                #pragma unroll
                for (int q = 0; q < 12; q++) T[q] += w2.y * a[q];
            }
        }

        float vx = vtx + lax, vy = vty + lay, vz = vtz + laz;
        vp0 = T[0] * vx + T[1] * vy + T[2]  * vz + T[3];
        vp1 = T[4] * vx + T[5] * vy + T[6]  * vz + T[7];
        vp2 = T[8] * vx + T[9] * vy + T[10] * vz + T[11];
    }

    // ---- phase 2: stage + balanced stores (sRot, 4 warps x 8 planes) ----
    __syncthreads();
    sVP[t * 3 + 0] = vp0;
    sVP[t * 3 + 1] = vp1;
    sVP[t * 3 + 2] = vp2;
    __syncthreads();

    const int block_f4 = blockIdx.x * F4_PER_BLK;    // multiple of 3
    const float4* sVP4 = (const float4*)sVP;
    const int lm = l % 3;

    #pragma unroll
    for (int i = 0; i < 3; i++) {
        int r = i * 32 + l;
        if (block_f4 + r < NQF) {
            float4 pv = sVP4[r];
            int m = lm + ((i * 32) % 3);             // compile-time addend
            if (m >= 3) m -= 3;
            const float4* rot = sRot + m * NB;
            #pragma unroll
            for (int k = 0; k < 8; k++) {
                int p = w + 4 * k;
                float4 a = rot[p];
                float4 o;
                o.x = pv.x + a.x; o.y = pv.y + a.y; o.z = pv.z + a.z; o.w = pv.w + a.w;
                __stcs(out + (size_t)p * NQF + block_f4 + r, o);
            }
        }
    }
}

// ---------------------------------------------------------------------------
extern "C" void kernel_launch(void* const* d_in, const int* in_sizes, int n_in,
                              void* d_out, int out_size)
{
    const float* pose         = (const float*)d_in[0]; // (34,3)
    const float* joints       = (const float*)d_in[1]; // (34,3)
    const float* weights      = (const float*)d_in[2]; // (V,34)
    const float* v_template   = (const float*)d_in[3]; // (V,3)
    const float* local_adjust = (const float*)d_in[4]; // (V,3)
    const float* displacement = (const float*)d_in[5]; // (1,3)
    const float* scale        = (const float*)d_in[6]; // (1,)
    const float* est          = (const float*)d_in[7]; // (B,3)
    float* out = (float*)d_out;
    (void)in_sizes; (void)n_in; (void)out_size;

    fused_lbs_kernel<<<NBLOCKS, BLK>>>(pose, joints, weights, v_template,
                                       local_adjust, displacement, scale, est,
                                       (float4*)out);
}

// round 13
// speedup vs baseline: 1.1718x; 1.1718x over previous
#include <cuda_runtime.h>
#include <math.h>
#include <stdint.h>

#define NJ 34
#define NV 500000
#define NB 32
#define NQF (NV * 3 / 4)       // 375000 output float4s per batch plane
#define BLK 128
#define NWARPS (BLK / 32)      // 4
#define NBLOCKS ((NV + BLK - 1) / BLK)   // 3907
#define F4_PER_BLK (BLK * 3 / 4)         // 96 float4s per plane per block
#define W_STRIDE 1088          // floats of weights per warp (32*34)

__constant__ int c_parents[NJ] = {
    -1, 0, 1, 2, 2, 4, 5, 6, 7, 8, 9, 7, 11, 12, 7, 14, 15, 2,
    17, 18, 19, 20, 21, 22, 20, 24, 25, 20, 27, 28, 0, 30, 0, 32
};

struct JointData {
    float A[NJ * 12];      // scaled 3x4 affines
    float Base[NB * 4];    // disp + est per plane
};

__device__ JointData g_JD;       // written by prep kernel
__constant__ JointData c_JD;     // memcpy'd before main kernel

// ---------------------------------------------------------------------------
// Prep kernel: rodrigues + parallel ancestor-chain FK + folding. ~1-2us.
// ---------------------------------------------------------------------------
__global__ void prep_kernel(const float* __restrict__ pose,
                            const float* __restrict__ joints,
                            const float* __restrict__ disp,
                            const float* __restrict__ scale,
                            const float* __restrict__ est)
{
    __shared__ float sT[NJ * 12];
    __shared__ float sJ[NJ * 3];
    int t = threadIdx.x;

    if (t < NJ * 3) sJ[t] = joints[t];
    if (t < NB * 3) {
        int b = t / 3, cc = t - b * 3;
        g_JD.Base[b * 4 + cc] = disp[cc] + est[t];
    }
    if (t < NB) g_JD.Base[t * 4 + 3] = 0.0f;
    __syncthreads();

    if (t < NJ) {
        float rx = pose[t * 3 + 0], ry = pose[t * 3 + 1], rz = pose[t * 3 + 2];
        float ang = sqrtf(rx * rx + ry * ry + rz * rz + 1e-8f);
        float inv = 1.0f / ang;
        float x = rx * inv, y = ry * inv, z = rz * inv;
        float s = sinf(ang), c = cosf(ang), oc = 1.0f - c;
        int p = c_parents[t];
        float tx = sJ[t * 3 + 0], ty = sJ[t * 3 + 1], tz = sJ[t * 3 + 2];
        if (p >= 0) { tx -= sJ[p * 3 + 0]; ty -= sJ[p * 3 + 1]; tz -= sJ[p * 3 + 2]; }
        float* T = sT + t * 12;
        T[0] = c + oc * x * x;      T[1] = oc * x * y - s * z;  T[2]  = oc * x * z + s * y;  T[3]  = tx;
        T[4] = oc * x * y + s * z;  T[5] = c + oc * y * y;      T[6]  = oc * y * z - s * x;  T[7]  = ty;
        T[8] = oc * x * z - s * y;  T[9] = oc * y * z + s * x;  T[10] = c + oc * z * z;      T[11] = tz;
    }
    __syncthreads();

    if (t < NJ) {
        int chain[16];
        int d = 0;
        for (int n = t; n >= 0; n = c_parents[n]) chain[d++] = n;
        float G[12];
        const float* Tr = sT + chain[d - 1] * 12;
        #pragma unroll
        for (int k = 0; k < 12; k++) G[k] = Tr[k];
        for (int k = d - 2; k >= 0; k--) {
            const float* Tc = sT + chain[k] * 12;
            float C[12];
            #pragma unroll
            for (int r = 0; r < 3; r++) {
                float g0 = G[r * 4 + 0], g1 = G[r * 4 + 1], g2 = G[r * 4 + 2], g3 = G[r * 4 + 3];
                C[r * 4 + 0] = g0 * Tc[0] + g1 * Tc[4] + g2 * Tc[8];
                C[r * 4 + 1] = g0 * Tc[1] + g1 * Tc[5] + g2 * Tc[9];
                C[r * 4 + 2] = g0 * Tc[2] + g1 * Tc[6] + g2 * Tc[10];
                C[r * 4 + 3] = g0 * Tc[3] + g1 * Tc[7] + g2 * Tc[11] + g3;
            }
            #pragma unroll
            for (int k2 = 0; k2 < 12; k2++) G[k2] = C[k2];
        }
        float sc = scale[0];
        float jx = sJ[t * 3 + 0], jy = sJ[t * 3 + 1], jz = sJ[t * 3 + 2];
        #pragma unroll
        for (int r = 0; r < 3; r++) {
            float tr = G[r * 4 + 0] * jx + G[r * 4 + 1] * jy + G[r * 4 + 2] * jz;
            g_JD.A[t * 12 + r * 4 + 0] = sc * G[r * 4 + 0];
            g_JD.A[t * 12 + r * 4 + 1] = sc * G[r * 4 + 1];
            g_JD.A[t * 12 + r * 4 + 2] = sc * G[r * 4 + 2];
            g_JD.A[t * 12 + r * 4 + 3] = sc * (G[r * 4 + 3] - tr);
        }
    }
}

// ---------------------------------------------------------------------------
// Main kernel: R10 structure minus phase 0; A + Base come from constant mem.
// ---------------------------------------------------------------------------
__global__ __launch_bounds__(BLK) void lbs_kernel(
    const float* __restrict__ weights,
    const float* __restrict__ v_template,
    const float* __restrict__ local_adjust,
    float4* __restrict__ out)
{
    __shared__ __align__(16) float sW[NWARPS * W_STRIDE];  // 17 KB staging
    __shared__ __align__(16) float sVP[BLK * 3];           // posed verts

    const int t = threadIdx.x;
    const int w = t >> 5;
    const int l = t & 31;

    // ---- warp-cooperative coalesced weight staging (R10 path) ----
    const int block_base = blockIdx.x * BLK;
    const int warp_base = block_base + w * 32;
    const int v = block_base + t;

    if (warp_base < NV) {
        const size_t f4_base = (size_t)warp_base * 34 / 4;
        const size_t f4_total = (size_t)NV * 34 / 4;
        const float4* srcw = (const float4*)weights;
        float4* dstw = (float4*)(sW + w * W_STRIDE);
        #pragma unroll
        for (int i = 0; i < 9; i++) {
            int idx = i * 32 + l;
            if (idx < 272 && f4_base + idx < f4_total)
                dstw[idx] = __ldcs(srcw + f4_base + idx);
        }
    }
    __syncwarp();

    // ---- skin (R5/R10 math; A from constant memory) ----
    float vp0 = 0.0f, vp1 = 0.0f, vp2 = 0.0f;
    if (v < NV) {
        float T[12];
        #pragma unroll
        for (int k = 0; k < 12; k++) T[k] = 0.0f;

        const float2* wp = (const float2*)(sW + w * W_STRIDE + l * 34);
        #pragma unroll
        for (int k = 0; k < 17; k++) {
            float2 w2 = wp[k];
            {
                float a[12];
                *(float4*)(a + 0) = *(const float4*)&c_JD.A[(2 * k) * 12 + 0];
                *(float4*)(a + 4) = *(const float4*)&c_JD.A[(2 * k) * 12 + 4];
                *(float4*)(a + 8) = *(const float4*)&c_JD.A[(2 * k) * 12 + 8];
                #pragma unroll
                for (int q = 0; q < 12; q++) T[q] += w2.x * a[q];
            }
            {
                float a[12];
                *(float4*)(a + 0) = *(const float4*)&c_JD.A[(2 * k + 1) * 12 + 0];
                *(float4*)(a + 4) = *(const float4*)&c_JD.A[(2 * k + 1) * 12 + 4];
                *(float4*)(a + 8) = *(const float4*)&c_JD.A[(2 * k + 1) * 12 + 8];
                #pragma unroll
                for (int q = 0; q < 12; q++) T[q] += w2.y * a[q];
            }
        }

        const float* vtp = v_template + (size_t)v * 3;
        const float* lap = local_adjust + (size_t)v * 3;
        float vx = __ldcs(vtp + 0) + __ldcs(lap + 0);
        float vy = __ldcs(vtp + 1) + __ldcs(lap + 1);
        float vz = __ldcs(vtp + 2) + __ldcs(lap + 2);

        vp0 = T[0] * vx + T[1] * vy + T[2]  * vz + T[3];
        vp1 = T[4] * vx + T[5] * vy + T[6]  * vz + T[7];
        vp2 = T[8] * vx + T[9] * vy + T[10] * vz + T[11];
    }

    // ---- stage + batched coalesced stores (exact R10 pattern) ----
    __syncthreads();
    sVP[t * 3 + 0] = vp0;
    sVP[t * 3 + 1] = vp1;
    sVP[t * 3 + 2] = vp2;
    __syncthreads();

    if (t < F4_PER_BLK) {
        int block_f4 = blockIdx.x * F4_PER_BLK;      // multiple of 3
        int valid = NQF - block_f4;
        if (t < valid) {
            float4 pv = ((const float4*)sVP)[t];
            int m = t % 3;
            #pragma unroll
            for (int b = 0; b < NB; b++) {
                float b0 = c_JD.Base[b * 4 + 0];
                float b1 = c_JD.Base[b * 4 + 1];
                float b2 = c_JD.Base[b * 4 + 2];
                float s0 = (m == 0) ? b0 : ((m == 1) ? b1 : b2);
                float s1 = (m == 0) ? b1 : ((m == 1) ? b2 : b0);
                float s2 = (m == 0) ? b2 : ((m == 1) ? b0 : b1);
                float4 o;
                o.x = pv.x + s0; o.y = pv.y + s1; o.z = pv.z + s2; o.w = pv.w + s0;
                __stcs(out + (size_t)b * NQF + block_f4 + t, o);
            }
        }
    }
}

// ---------------------------------------------------------------------------
extern "C" void kernel_launch(void* const* d_in, const int* in_sizes, int n_in,
                              void* d_out, int out_size)
{
    const float* pose         = (const float*)d_in[0]; // (34,3)
    const float* joints       = (const float*)d_in[1]; // (34,3)
    const float* weights      = (const float*)d_in[2]; // (V,34)
    const float* v_template   = (const float*)d_in[3]; // (V,3)
    const float* local_adjust = (const float*)d_in[4]; // (V,3)
    const float* displacement = (const float*)d_in[5]; // (1,3)
    const float* scale        = (const float*)d_in[6]; // (1,)
    const float* est          = (const float*)d_in[7]; // (B,3)
    float* out = (float*)d_out;
    (void)in_sizes; (void)n_in; (void)out_size;

    prep_kernel<<<1, 128>>>(pose, joints, displacement, scale, est);

    void* g_addr = nullptr;
    cudaGetSymbolAddress(&g_addr, g_JD);
    cudaMemcpyToSymbolAsync(c_JD, g_addr, sizeof(JointData), 0,
                            cudaMemcpyDeviceToDevice, 0);

    lbs_kernel<<<NBLOCKS, BLK>>>(weights, v_template, local_adjust,
                                 (float4*)out);
}

// round 14
// speedup vs baseline: 1.1724x; 1.0005x over previous
#include <cuda_runtime.h>
#include <math.h>
#include <stdint.h>

#define NJ 34
#define NV 500000
#define NB 32
#define NQF (NV * 3 / 4)       // 375000 output float4s per batch plane
#define BLK 128
#define NWARPS (BLK / 32)      // 4
#define NBLOCKS ((NV + BLK - 1) / BLK)   // 3907
#define F4_PER_BLK (BLK * 3 / 4)         // 96 float4s per plane per block
#define W_STRIDE 1088          // floats of weights per warp (32*34)

__constant__ int c_parents[NJ] = {
    -1, 0, 1, 2, 2, 4, 5, 6, 7, 8, 9, 7, 11, 12, 7, 14, 15, 2,
    17, 18, 19, 20, 21, 22, 20, 24, 25, 20, 27, 28, 0, 30, 0, 32
};

struct JointData {
    float A[NJ * 12];      // scaled 3x4 affines
    float Base[NB * 4];    // disp + est per plane
};

__device__ JointData g_JD;       // written by prep kernel
__constant__ JointData c_JD;     // memcpy'd before main kernel

// ---------------------------------------------------------------------------
// Prep kernel: all input loads issued concurrently at the top (one DRAM
// round), then rodrigues + parallel ancestor-chain FK + folding.
// ---------------------------------------------------------------------------
__global__ void prep_kernel(const float* __restrict__ pose,
                            const float* __restrict__ joints,
                            const float* __restrict__ disp,
                            const float* __restrict__ scale,
                            const float* __restrict__ est)
{
    __shared__ float sT[NJ * 12];
    __shared__ float sJ[NJ * 3];
    int t = threadIdx.x;

    // ---- issue ALL global loads up front (concurrent, MLP) ----
    float px = 0.f, py = 0.f, pz = 0.f, sc = 1.f;
    if (t < NJ) {
        px = pose[t * 3 + 0];
        py = pose[t * 3 + 1];
        pz = pose[t * 3 + 2];
        sc = scale[0];
    }
    if (t < NJ * 3) sJ[t] = joints[t];
    if (t < NB * 3) {
        int b = t / 3, cc = t - b * 3;
        g_JD.Base[b * 4 + cc] = disp[cc] + est[t];
    }
    if (t < NB) g_JD.Base[t * 4 + 3] = 0.0f;
    __syncthreads();

    if (t < NJ) {
        float ang = sqrtf(px * px + py * py + pz * pz + 1e-8f);
        float inv = 1.0f / ang;
        float x = px * inv, y = py * inv, z = pz * inv;
        float s = sinf(ang), c = cosf(ang), oc = 1.0f - c;
        int p = c_parents[t];
        float tx = sJ[t * 3 + 0], ty = sJ[t * 3 + 1], tz = sJ[t * 3 + 2];
        if (p >= 0) { tx -= sJ[p * 3 + 0]; ty -= sJ[p * 3 + 1]; tz -= sJ[p * 3 + 2]; }
        float* T = sT + t * 12;
        T[0] = c + oc * x * x;      T[1] = oc * x * y - s * z;  T[2]  = oc * x * z + s * y;  T[3]  = tx;
        T[4] = oc * x * y + s * z;  T[5] = c + oc * y * y;      T[6]  = oc * y * z - s * x;  T[7]  = ty;
        T[8] = oc * x * z - s * y;  T[9] = oc * y * z + s * x;  T[10] = c + oc * z * z;      T[11] = tz;
    }
    __syncthreads();

    if (t < NJ) {
        int chain[16];
        int d = 0;
        for (int n = t; n >= 0; n = c_parents[n]) chain[d++] = n;
        float G[12];
        const float* Tr = sT + chain[d - 1] * 12;
        #pragma unroll
        for (int k = 0; k < 12; k++) G[k] = Tr[k];
        for (int k = d - 2; k >= 0; k--) {
            const float* Tc = sT + chain[k] * 12;
            float C[12];
            #pragma unroll
            for (int r = 0; r < 3; r++) {
                float g0 = G[r * 4 + 0], g1 = G[r * 4 + 1], g2 = G[r * 4 + 2], g3 = G[r * 4 + 3];
                C[r * 4 + 0] = g0 * Tc[0] + g1 * Tc[4] + g2 * Tc[8];
                C[r * 4 + 1] = g0 * Tc[1] + g1 * Tc[5] + g2 * Tc[9];
                C[r * 4 + 2] = g0 * Tc[2] + g1 * Tc[6] + g2 * Tc[10];
                C[r * 4 + 3] = g0 * Tc[3] + g1 * Tc[7] + g2 * Tc[11] + g3;
            }
            #pragma unroll
            for (int k2 = 0; k2 < 12; k2++) G[k2] = C[k2];
        }
        float jx = sJ[t * 3 + 0], jy = sJ[t * 3 + 1], jz = sJ[t * 3 + 2];
        #pragma unroll
        for (int r = 0; r < 3; r++) {
            float tr = G[r * 4 + 0] * jx + G[r * 4 + 1] * jy + G[r * 4 + 2] * jz;
            g_JD.A[t * 12 + r * 4 + 0] = sc * G[r * 4 + 0];
            g_JD.A[t * 12 + r * 4 + 1] = sc * G[r * 4 + 1];
            g_JD.A[t * 12 + r * 4 + 2] = sc * G[r * 4 + 2];
            g_JD.A[t * 12 + r * 4 + 3] = sc * (G[r * 4 + 3] - tr);
        }
    }
}

// ---------------------------------------------------------------------------
// Main kernel: R13 structure; A + Base from constant memory; vt/la hoisted
// before the staging syncwarp so their latency overlaps the weight LDGs.
// ---------------------------------------------------------------------------
__global__ __launch_bounds__(BLK) void lbs_kernel(
    const float* __restrict__ weights,
    const float* __restrict__ v_template,
    const float* __restrict__ local_adjust,
    float4* __restrict__ out)
{
    __shared__ __align__(16) float sW[NWARPS * W_STRIDE];  // 17 KB staging
    __shared__ __align__(16) float sVP[BLK * 3];           // posed verts

    const int t = threadIdx.x;
    const int w = t >> 5;
    const int l = t & 31;

    // ---- warp-cooperative coalesced weight staging ----
    const int block_base = blockIdx.x * BLK;
    const int warp_base = block_base + w * 32;
    const int v = block_base + t;

    if (warp_base < NV) {
        const size_t f4_base = (size_t)warp_base * 34 / 4;
        const size_t f4_total = (size_t)NV * 34 / 4;
        const float4* srcw = (const float4*)weights;
        float4* dstw = (float4*)(sW + w * W_STRIDE);
        #pragma unroll
        for (int i = 0; i < 9; i++) {
            int idx = i * 32 + l;
            if (idx < 272 && f4_base + idx < f4_total)
                dstw[idx] = __ldcs(srcw + f4_base + idx);
        }
    }

    // vt/la loads in flight while staging completes
    float vtx = 0.f, vty = 0.f, vtz = 0.f, lax = 0.f, lay = 0.f, laz = 0.f;
    if (v < NV) {
        const float* vtp = v_template + (size_t)v * 3;
        const float* lap = local_adjust + (size_t)v * 3;
        vtx = __ldcs(vtp + 0); vty = __ldcs(vtp + 1); vtz = __ldcs(vtp + 2);
        lax = __ldcs(lap + 0); lay = __ldcs(lap + 1); laz = __ldcs(lap + 2);
    }
    __syncwarp();

    // ---- skin (A from constant memory) ----
    float vp0 = 0.0f, vp1 = 0.0f, vp2 = 0.0f;
    if (v < NV) {
        float T[12];
        #pragma unroll
        for (int k = 0; k < 12; k++) T[k] = 0.0f;

        const float2* wp = (const float2*)(sW + w * W_STRIDE + l * 34);
        #pragma unroll
        for (int k = 0; k < 17; k++) {
            float2 w2 = wp[k];
            {
                float a[12];
                *(float4*)(a + 0) = *(const float4*)&c_JD.A[(2 * k) * 12 + 0];
                *(float4*)(a + 4) = *(const float4*)&c_JD.A[(2 * k) * 12 + 4];
                *(float4*)(a + 8) = *(const float4*)&c_JD.A[(2 * k) * 12 + 8];
                #pragma unroll
                for (int q = 0; q < 12; q++) T[q] += w2.x * a[q];
            }
            {
                float a[12];
                *(float4*)(a + 0) = *(const float4*)&c_JD.A[(2 * k + 1) * 12 + 0];
                *(float4*)(a + 4) = *(const float4*)&c_JD.A[(2 * k + 1) * 12 + 4];
                *(float4*)(a + 8) = *(const float4*)&c_JD.A[(2 * k + 1) * 12 + 8];
                #pragma unroll
                for (int q = 0; q < 12; q++) T[q] += w2.y * a[q];
            }
        }

        float vx = vtx + lax, vy = vty + lay, vz = vtz + laz;
        vp0 = T[0] * vx + T[1] * vy + T[2]  * vz + T[3];
        vp1 = T[4] * vx + T[5] * vy + T[6]  * vz + T[7];
        vp2 = T[8] * vx + T[9] * vy + T[10] * vz + T[11];
    }

    // ---- stage + batched coalesced stores (exact R13/R10 pattern) ----
    __syncthreads();
    sVP[t * 3 + 0] = vp0;
    sVP[t * 3 + 1] = vp1;
    sVP[t * 3 + 2] = vp2;
    __syncthreads();

    if (t < F4_PER_BLK) {
        int block_f4 = blockIdx.x * F4_PER_BLK;      // multiple of 3
        int valid = NQF - block_f4;
        if (t < valid) {
            float4 pv = ((const float4*)sVP)[t];
            int m = t % 3;
            #pragma unroll
            for (int b = 0; b < NB; b++) {
                float b0 = c_JD.Base[b * 4 + 0];
                float b1 = c_JD.Base[b * 4 + 1];
                float b2 = c_JD.Base[b * 4 + 2];
                float s0 = (m == 0) ? b0 : ((m == 1) ? b1 : b2);
                float s1 = (m == 0) ? b1 : ((m == 1) ? b2 : b0);
                float s2 = (m == 0) ? b2 : ((m == 1) ? b0 : b1);
                float4 o;
                o.x = pv.x + s0; o.y = pv.y + s1; o.z = pv.z + s2; o.w = pv.w + s0;
                __stcs(out + (size_t)b * NQF + block_f4 + t, o);
            }
        }
    }
}

// ---------------------------------------------------------------------------
extern "C" void kernel_launch(void* const* d_in, const int* in_sizes, int n_in,
                              void* d_out, int out_size)
{
    const float* pose         = (const float*)d_in[0]; // (34,3)
    const float* joints       = (const float*)d_in[1]; // (34,3)
    const float* weights      = (const float*)d_in[2]; // (V,34)
    const float* v_template   = (const float*)d_in[3]; // (V,3)
    const float* local_adjust = (const float*)d_in[4]; // (V,3)
    const float* displacement = (const float*)d_in[5]; // (1,3)
    const float* scale        = (const float*)d_in[6]; // (1,)
    const float* est          = (const float*)d_in[7]; // (B,3)
    float* out = (float*)d_out;
    (void)in_sizes; (void)n_in; (void)out_size;

    prep_kernel<<<1, 128>>>(pose, joints, displacement, scale, est);

    void* g_addr = nullptr;
    cudaGetSymbolAddress(&g_addr, g_JD);
    cudaMemcpyToSymbolAsync(c_JD, g_addr, sizeof(JointData), 0,
                            cudaMemcpyDeviceToDevice, 0);

    lbs_kernel<<<NBLOCKS, BLK>>>(weights, v_template, local_adjust,
                                 (float4*)out);
}

// round 15
// speedup vs baseline: 1.2096x; 1.0317x over previous
#include <cuda_runtime.h>
#include <math.h>
#include <stdint.h>

#define NJ 34
#define NV 500000
#define NB 32
#define NQF (NV * 3 / 4)       // 375000 output float4s per batch plane
#define BLK 128
#define NWARPS (BLK / 32)      // 4
#define NBLOCKS ((NV + BLK - 1) / BLK)   // 3907
#define F4_PER_BLK (BLK * 3 / 4)         // 96 float4s per plane per block
#define W_STRIDE 1088          // floats of weights per warp (32*34)

__constant__ int c_parents[NJ] = {
    -1, 0, 1, 2, 2, 4, 5, 6, 7, 8, 9, 7, 11, 12, 7, 14, 15, 2,
    17, 18, 19, 20, 21, 22, 20, 24, 25, 20, 27, 28, 0, 30, 0, 32
};

struct JointData {
    float A[NJ * 12];      // scaled 3x4 affines
    float Base[NB * 4];    // disp + est per plane
};

__constant__ JointData c_JD;     // written DIRECTLY by prep kernel via
                                 // its backing-store address (no memcpy node)

// ---------------------------------------------------------------------------
// Prep kernel: all input loads issued concurrently up front, rodrigues +
// parallel ancestor-chain FK + folding; writes straight into c_JD's
// backing store through the pointer passed from the host.
// ---------------------------------------------------------------------------
__global__ void prep_kernel(JointData* __restrict__ jd,
                            const float* __restrict__ pose,
                            const float* __restrict__ joints,
                            const float* __restrict__ disp,
                            const float* __restrict__ scale,
                            const float* __restrict__ est)
{
    __shared__ float sT[NJ * 12];
    __shared__ float sJ[NJ * 3];
    int t = threadIdx.x;

    // ---- issue ALL global loads up front (concurrent, MLP) ----
    float px = 0.f, py = 0.f, pz = 0.f, sc = 1.f;
    if (t < NJ) {
        px = pose[t * 3 + 0];
        py = pose[t * 3 + 1];
        pz = pose[t * 3 + 2];
        sc = scale[0];
    }
    if (t < NJ * 3) sJ[t] = joints[t];
    if (t < NB * 3) {
        int b = t / 3, cc = t - b * 3;
        jd->Base[b * 4 + cc] = disp[cc] + est[t];
    }
    if (t < NB) jd->Base[t * 4 + 3] = 0.0f;
    __syncthreads();

    if (t < NJ) {
        float ang = sqrtf(px * px + py * py + pz * pz + 1e-8f);
        float inv = 1.0f / ang;
        float x = px * inv, y = py * inv, z = pz * inv;
        float s = sinf(ang), c = cosf(ang), oc = 1.0f - c;
        int p = c_parents[t];
        float tx = sJ[t * 3 + 0], ty = sJ[t * 3 + 1], tz = sJ[t * 3 + 2];
        if (p >= 0) { tx -= sJ[p * 3 + 0]; ty -= sJ[p * 3 + 1]; tz -= sJ[p * 3 + 2]; }
        float* T = sT + t * 12;
        T[0] = c + oc * x * x;      T[1] = oc * x * y - s * z;  T[2]  = oc * x * z + s * y;  T[3]  = tx;
        T[4] = oc * x * y + s * z;  T[5] = c + oc * y * y;      T[6]  = oc * y * z - s * x;  T[7]  = ty;
        T[8] = oc * x * z - s * y;  T[9] = oc * y * z + s * x;  T[10] = c + oc * z * z;      T[11] = tz;
    }
    __syncthreads();

    if (t < NJ) {
        int chain[16];
        int d = 0;
        for (int n = t; n >= 0; n = c_parents[n]) chain[d++] = n;
        float G[12];
        const float* Tr = sT + chain[d - 1] * 12;
        #pragma unroll
        for (int k = 0; k < 12; k++) G[k] = Tr[k];
        for (int k = d - 2; k >= 0; k--) {
            const float* Tc = sT + chain[k] * 12;
            float C[12];
            #pragma unroll
            for (int r = 0; r < 3; r++) {
                float g0 = G[r * 4 + 0], g1 = G[r * 4 + 1], g2 = G[r * 4 + 2], g3 = G[r * 4 + 3];
                C[r * 4 + 0] = g0 * Tc[0] + g1 * Tc[4] + g2 * Tc[8];
                C[r * 4 + 1] = g0 * Tc[1] + g1 * Tc[5] + g2 * Tc[9];
                C[r * 4 + 2] = g0 * Tc[2] + g1 * Tc[6] + g2 * Tc[10];
                C[r * 4 + 3] = g0 * Tc[3] + g1 * Tc[7] + g2 * Tc[11] + g3;
            }
            #pragma unroll
            for (int k2 = 0; k2 < 12; k2++) G[k2] = C[k2];
        }
        float jx = sJ[t * 3 + 0], jy = sJ[t * 3 + 1], jz = sJ[t * 3 + 2];
        #pragma unroll
        for (int r = 0; r < 3; r++) {
            float tr = G[r * 4 + 0] * jx + G[r * 4 + 1] * jy + G[r * 4 + 2] * jz;
            jd->A[t * 12 + r * 4 + 0] = sc * G[r * 4 + 0];
            jd->A[t * 12 + r * 4 + 1] = sc * G[r * 4 + 1];
            jd->A[t * 12 + r * 4 + 2] = sc * G[r * 4 + 2];
            jd->A[t * 12 + r * 4 + 3] = sc * (G[r * 4 + 3] - tr);
        }
    }
}

// ---------------------------------------------------------------------------
// Main kernel: identical to R14 (at the machine floor). A + Base from the
// constant port; warp-staged coalesced weights; batched coalesced stores.
// ---------------------------------------------------------------------------
__global__ __launch_bounds__(BLK) void lbs_kernel(
    const float* __restrict__ weights,
    const float* __restrict__ v_template,
    const float* __restrict__ local_adjust,
    float4* __restrict__ out)
{
    __shared__ __align__(16) float sW[NWARPS * W_STRIDE];  // 17 KB staging
    __shared__ __align__(16) float sVP[BLK * 3];           // posed verts

    const int t = threadIdx.x;
    const int w = t >> 5;
    const int l = t & 31;

    // ---- warp-cooperative coalesced weight staging ----
    const int block_base = blockIdx.x * BLK;
    const int warp_base = block_base + w * 32;
    const int v = block_base + t;

    if (warp_base < NV) {
        const size_t f4_base = (size_t)warp_base * 34 / 4;
        const size_t f4_total = (size_t)NV * 34 / 4;
        const float4* srcw = (const float4*)weights;
        float4* dstw = (float4*)(sW + w * W_STRIDE);
        #pragma unroll
        for (int i = 0; i < 9; i++) {
            int idx = i * 32 + l;
            if (idx < 272 && f4_base + idx < f4_total)
                dstw[idx] = __ldcs(srcw + f4_base + idx);
        }
    }

    // vt/la loads in flight while staging completes
    float vtx = 0.f, vty = 0.f, vtz = 0.f, lax = 0.f, lay = 0.f, laz = 0.f;
    if (v < NV) {
        const float* vtp = v_template + (size_t)v * 3;
        const float* lap = local_adjust + (size_t)v * 3;
        vtx = __ldcs(vtp + 0); vty = __ldcs(vtp + 1); vtz = __ldcs(vtp + 2);
        lax = __ldcs(lap + 0); lay = __ldcs(lap + 1); laz = __ldcs(lap + 2);
    }
    __syncwarp();

    // ---- skin (A from constant memory) ----
    float vp0 = 0.0f, vp1 = 0.0f, vp2 = 0.0f;
    if (v < NV) {
        float T[12];
        #pragma unroll
        for (int k = 0; k < 12; k++) T[k] = 0.0f;

        const float2* wp = (const float2*)(sW + w * W_STRIDE + l * 34);
        #pragma unroll
        for (int k = 0; k < 17; k++) {
            float2 w2 = wp[k];
            {
                float a[12];
                *(float4*)(a + 0) = *(const float4*)&c_JD.A[(2 * k) * 12 + 0];
                *(float4*)(a + 4) = *(const float4*)&c_JD.A[(2 * k) * 12 + 4];
                *(float4*)(a + 8) = *(const float4*)&c_JD.A[(2 * k) * 12 + 8];
                #pragma unroll
                for (int q = 0; q < 12; q++) T[q] += w2.x * a[q];
            }
            {
                float a[12];
                *(float4*)(a + 0) = *(const float4*)&c_JD.A[(2 * k + 1) * 12 + 0];
                *(float4*)(a + 4) = *(const float4*)&c_JD.A[(2 * k + 1) * 12 + 4];
                *(float4*)(a + 8) = *(const float4*)&c_JD.A[(2 * k + 1) * 12 + 8];
                #pragma unroll
                for (int q = 0; q < 12; q++) T[q] += w2.y * a[q];
            }
        }

        float vx = vtx + lax, vy = vty + lay, vz = vtz + laz;
        vp0 = T[0] * vx + T[1] * vy + T[2]  * vz + T[3];
        vp1 = T[4] * vx + T[5] * vy + T[6]  * vz + T[7];
        vp2 = T[8] * vx + T[9] * vy + T[10] * vz + T[11];
    }

    // ---- stage + batched coalesced stores ----
    __syncthreads();
    sVP[t * 3 + 0] = vp0;
    sVP[t * 3 + 1] = vp1;
    sVP[t * 3 + 2] = vp2;
    __syncthreads();

    if (t < F4_PER_BLK) {
        int block_f4 = blockIdx.x * F4_PER_BLK;      // multiple of 3
        int valid = NQF - block_f4;
        if (t < valid) {
            float4 pv = ((const float4*)sVP)[t];
            int m = t % 3;
            #pragma unroll
            for (int b = 0; b < NB; b++) {
                float b0 = c_JD.Base[b * 4 + 0];
                float b1 = c_JD.Base[b * 4 + 1];
                float b2 = c_JD.Base[b * 4 + 2];
                float s0 = (m == 0) ? b0 : ((m == 1) ? b1 : b2);
                float s1 = (m == 0) ? b1 : ((m == 1) ? b2 : b0);
                float s2 = (m == 0) ? b2 : ((m == 1) ? b0 : b1);
                float4 o;
                o.x = pv.x + s0; o.y = pv.y + s1; o.z = pv.z + s2; o.w = pv.w + s0;
                __stcs(out + (size_t)b * NQF + block_f4 + t, o);
            }
        }
    }
}

// ---------------------------------------------------------------------------
extern "C" void kernel_launch(void* const* d_in, const int* in_sizes, int n_in,
                              void* d_out, int out_size)
{
    const float* pose         = (const float*)d_in[0]; // (34,3)
    const float* joints       = (const float*)d_in[1]; // (34,3)
    const float* weights      = (const float*)d_in[2]; // (V,34)
    const float* v_template   = (const float*)d_in[3]; // (V,3)
    const float* local_adjust = (const float*)d_in[4]; // (V,3)
    const float* displacement = (const float*)d_in[5]; // (1,3)
    const float* scale        = (const float*)d_in[6]; // (1,)
    const float* est          = (const float*)d_in[7]; // (B,3)
    float* out = (float*)d_out;
    (void)in_sizes; (void)n_in; (void)out_size;

    // Backing store of the __constant__ symbol; prep writes it directly.
    // Resolved on every call (cheap driver lookup, no allocation).
    void* jd_addr = nullptr;
    cudaGetSymbolAddress(&jd_addr, c_JD);

    prep_kernel<<<1, 128>>>((JointData*)jd_addr, pose, joints, displacement,
                            scale, est);

    lbs_kernel<<<NBLOCKS, BLK>>>(weights, v_template, local_adjust,
                                 (float4*)out);
}

// round 16
// speedup vs baseline: 1.2136x; 1.0033x over previous
#include <cuda_runtime.h>
#include <math.h>
#include <stdint.h>

#define NJ 34
#define NV 500000
#define NB 32
#define NQF (NV * 3 / 4)       // 375000 output float4s per batch plane
#define BLK 128
#define NWARPS (BLK / 32)      // 4
#define NBLOCKS ((NV + BLK - 1) / BLK)   // 3907
#define F4_PER_BLK (BLK * 3 / 4)         // 96 float4s per plane per block
#define W_STRIDE 1088          // floats of weights per warp (32*34)

__constant__ int c_parents[NJ] = {
    -1, 0, 1, 2, 2, 4, 5, 6, 7, 8, 9, 7, 11, 12, 7, 14, 15, 2,
    17, 18, 19, 20, 21, 22, 20, 24, 25, 20, 27, 28, 0, 30, 0, 32
};

struct JointData {
    float A[NJ * 12];      // scaled 3x4 affines
    float Base[NB * 4];    // disp + est per plane
};

__constant__ JointData c_JD;     // backing store written directly by prep

// ---------------------------------------------------------------------------
// Prep kernel (R15): concurrent input loads, rodrigues + chain FK + folding,
// writes straight into c_JD's backing store.
// ---------------------------------------------------------------------------
__global__ void prep_kernel(JointData* __restrict__ jd,
                            const float* __restrict__ pose,
                            const float* __restrict__ joints,
                            const float* __restrict__ disp,
                            const float* __restrict__ scale,
                            const float* __restrict__ est)
{
    __shared__ float sT[NJ * 12];
    __shared__ float sJ[NJ * 3];
    int t = threadIdx.x;

    float px = 0.f, py = 0.f, pz = 0.f, sc = 1.f;
    if (t < NJ) {
        px = pose[t * 3 + 0];
        py = pose[t * 3 + 1];
        pz = pose[t * 3 + 2];
        sc = scale[0];
    }
    if (t < NJ * 3) sJ[t] = joints[t];
    if (t < NB * 3) {
        int b = t / 3, cc = t - b * 3;
        jd->Base[b * 4 + cc] = disp[cc] + est[t];
    }
    if (t < NB) jd->Base[t * 4 + 3] = 0.0f;
    __syncthreads();

    if (t < NJ) {
        float ang = sqrtf(px * px + py * py + pz * pz + 1e-8f);
        float inv = 1.0f / ang;
        float x = px * inv, y = py * inv, z = pz * inv;
        float s = sinf(ang), c = cosf(ang), oc = 1.0f - c;
        int p = c_parents[t];
        float tx = sJ[t * 3 + 0], ty = sJ[t * 3 + 1], tz = sJ[t * 3 + 2];
        if (p >= 0) { tx -= sJ[p * 3 + 0]; ty -= sJ[p * 3 + 1]; tz -= sJ[p * 3 + 2]; }
        float* T = sT + t * 12;
        T[0] = c + oc * x * x;      T[1] = oc * x * y - s * z;  T[2]  = oc * x * z + s * y;  T[3]  = tx;
        T[4] = oc * x * y + s * z;  T[5] = c + oc * y * y;      T[6]  = oc * y * z - s * x;  T[7]  = ty;
        T[8] = oc * x * z - s * y;  T[9] = oc * y * z + s * x;  T[10] = c + oc * z * z;      T[11] = tz;
    }
    __syncthreads();

    if (t < NJ) {
        int chain[16];
        int d = 0;
        for (int n = t; n >= 0; n = c_parents[n]) chain[d++] = n;
        float G[12];
        const float* Tr = sT + chain[d - 1] * 12;
        #pragma unroll
        for (int k = 0; k < 12; k++) G[k] = Tr[k];
        for (int k = d - 2; k >= 0; k--) {
            const float* Tc = sT + chain[k] * 12;
            float C[12];
            #pragma unroll
            for (int r = 0; r < 3; r++) {
                float g0 = G[r * 4 + 0], g1 = G[r * 4 + 1], g2 = G[r * 4 + 2], g3 = G[r * 4 + 3];
                C[r * 4 + 0] = g0 * Tc[0] + g1 * Tc[4] + g2 * Tc[8];
                C[r * 4 + 1] = g0 * Tc[1] + g1 * Tc[5] + g2 * Tc[9];
                C[r * 4 + 2] = g0 * Tc[2] + g1 * Tc[6] + g2 * Tc[10];
                C[r * 4 + 3] = g0 * Tc[3] + g1 * Tc[7] + g2 * Tc[11] + g3;
            }
            #pragma unroll
            for (int k2 = 0; k2 < 12; k2++) G[k2] = C[k2];
        }
        float jx = sJ[t * 3 + 0], jy = sJ[t * 3 + 1], jz = sJ[t * 3 + 2];
        #pragma unroll
        for (int r = 0; r < 3; r++) {
            float tr = G[r * 4 + 0] * jx + G[r * 4 + 1] * jy + G[r * 4 + 2] * jz;
            jd->A[t * 12 + r * 4 + 0] = sc * G[r * 4 + 0];
            jd->A[t * 12 + r * 4 + 1] = sc * G[r * 4 + 1];
            jd->A[t * 12 + r * 4 + 2] = sc * G[r * 4 + 2];
            jd->A[t * 12 + r * 4 + 3] = sc * (G[r * 4 + 3] - tr);
        }
    }
}

// ---------------------------------------------------------------------------
// Main kernel (R14/R15 body) launched with PDL: the c_JD-independent
// prologue (weight staging + vt/la loads) overlaps prep; the grid-dependency
// sync gates the first constant read.
// ---------------------------------------------------------------------------
__global__ __launch_bounds__(BLK) void lbs_kernel(
    const float* __restrict__ weights,
    const float* __restrict__ v_template,
    const float* __restrict__ local_adjust,
    float4* __restrict__ out)
{
    __shared__ __align__(16) float sW[NWARPS * W_STRIDE];  // 17 KB staging
    __shared__ __align__(16) float sVP[BLK * 3];           // posed verts

    const int t = threadIdx.x;
    const int w = t >> 5;
    const int l = t & 31;

    // ---- c_JD-independent prologue (overlaps prep under PDL) ----
    const int block_base = blockIdx.x * BLK;
    const int warp_base = block_base + w * 32;
    const int v = block_base + t;

    if (warp_base < NV) {
        const size_t f4_base = (size_t)warp_base * 34 / 4;
        const size_t f4_total = (size_t)NV * 34 / 4;
        const float4* srcw = (const float4*)weights;
        float4* dstw = (float4*)(sW + w * W_STRIDE);
        #pragma unroll
        for (int i = 0; i < 9; i++) {
            int idx = i * 32 + l;
            if (idx < 272 && f4_base + idx < f4_total)
                dstw[idx] = __ldcs(srcw + f4_base + idx);
        }
    }

    float vtx = 0.f, vty = 0.f, vtz = 0.f, lax = 0.f, lay = 0.f, laz = 0.f;
    if (v < NV) {
        const float* vtp = v_template + (size_t)v * 3;
        const float* lap = local_adjust + (size_t)v * 3;
        vtx = __ldcs(vtp + 0); vty = __ldcs(vtp + 1); vtz = __ldcs(vtp + 2);
        lax = __ldcs(lap + 0); lay = __ldcs(lap + 1); laz = __ldcs(lap + 2);
    }

    // ---- wait for prep's grid (c_JD backing store now L2-visible) ----
    cudaGridDependencySynchronize();
    __syncwarp();

    // ---- skin (A from constant memory) ----
    float vp0 = 0.0f, vp1 = 0.0f, vp2 = 0.0f;
    if (v < NV) {
        float T[12];
        #pragma unroll
        for (int k = 0; k < 12; k++) T[k] = 0.0f;

        const float2* wp = (const float2*)(sW + w * W_STRIDE + l * 34);
        #pragma unroll
        for (int k = 0; k < 17; k++) {
            float2 w2 = wp[k];
            {
                float a[12];
                *(float4*)(a + 0) = *(const float4*)&c_JD.A[(2 * k) * 12 + 0];
                *(float4*)(a + 4) = *(const float4*)&c_JD.A[(2 * k) * 12 + 4];
                *(float4*)(a + 8) = *(const float4*)&c_JD.A[(2 * k) * 12 + 8];
                #pragma unroll
                for (int q = 0; q < 12; q++) T[q] += w2.x * a[q];
            }
            {
                float a[12];
                *(float4*)(a + 0) = *(const float4*)&c_JD.A[(2 * k + 1) * 12 + 0];
                *(float4*)(a + 4) = *(const float4*)&c_JD.A[(2 * k + 1) * 12 + 4];
                *(float4*)(a + 8) = *(const float4*)&c_JD.A[(2 * k + 1) * 12 + 8];
                #pragma unroll
                for (int q = 0; q < 12; q++) T[q] += w2.y * a[q];
            }
        }

        float vx = vtx + lax, vy = vty + lay, vz = vtz + laz;
        vp0 = T[0] * vx + T[1] * vy + T[2]  * vz + T[3];
        vp1 = T[4] * vx + T[5] * vy + T[6]  * vz + T[7];
        vp2 = T[8] * vx + T[9] * vy + T[10] * vz + T[11];
    }

    // ---- stage + batched coalesced stores (unchanged) ----
    __syncthreads();
    sVP[t * 3 + 0] = vp0;
    sVP[t * 3 + 1] = vp1;
    sVP[t * 3 + 2] = vp2;
    __syncthreads();

    if (t < F4_PER_BLK) {
        int block_f4 = blockIdx.x * F4_PER_BLK;      // multiple of 3
        int valid = NQF - block_f4;
        if (t < valid) {
            float4 pv = ((const float4*)sVP)[t];
            int m = t % 3;
            #pragma unroll
            for (int b = 0; b < NB; b++) {
                float b0 = c_JD.Base[b * 4 + 0];
                float b1 = c_JD.Base[b * 4 + 1];
                float b2 = c_JD.Base[b * 4 + 2];
                float s0 = (m == 0) ? b0 : ((m == 1) ? b1 : b2);
                float s1 = (m == 0) ? b1 : ((m == 1) ? b2 : b0);
                float s2 = (m == 0) ? b2 : ((m == 1) ? b0 : b1);
                float4 o;
                o.x = pv.x + s0; o.y = pv.y + s1; o.z = pv.z + s2; o.w = pv.w + s0;
                __stcs(out + (size_t)b * NQF + block_f4 + t, o);
            }
        }
    }
}

// ---------------------------------------------------------------------------
extern "C" void kernel_launch(void* const* d_in, const int* in_sizes, int n_in,
                              void* d_out, int out_size)
{
    const float* pose         = (const float*)d_in[0]; // (34,3)
    const float* joints       = (const float*)d_in[1]; // (34,3)
    const float* weights      = (const float*)d_in[2]; // (V,34)
    const float* v_template   = (const float*)d_in[3]; // (V,3)
    const float* local_adjust = (const float*)d_in[4]; // (V,3)
    const float* displacement = (const float*)d_in[5]; // (1,3)
    const float* scale        = (const float*)d_in[6]; // (1,)
    const float* est          = (const float*)d_in[7]; // (B,3)
    float* out = (float*)d_out;
    (void)in_sizes; (void)n_in; (void)out_size;

    void* jd_addr = nullptr;
    cudaGetSymbolAddress(&jd_addr, c_JD);

    prep_kernel<<<1, 128>>>((JointData*)jd_addr, pose, joints, displacement,
                            scale, est);

    // PDL launch: lbs may begin before prep completes; the in-kernel
    // cudaGridDependencySynchronize() gates all c_JD reads.
    cudaLaunchConfig_t cfg = {};
    cfg.gridDim = dim3(NBLOCKS, 1, 1);
    cfg.blockDim = dim3(BLK, 1, 1);
    cfg.dynamicSmemBytes = 0;
    cfg.stream = 0;
    cudaLaunchAttribute attrs[1];
    attrs[0].id = cudaLaunchAttributeProgrammaticStreamSerialization;
    attrs[0].val.programmaticStreamSerializationAllowed = 1;
    cfg.attrs = attrs;
    cfg.numAttrs = 1;
    cudaLaunchKernelEx(&cfg, lbs_kernel, weights, v_template, local_adjust,
                       (float4*)out);
}